// round 3
// baseline (speedup 1.0000x reference)
#include <cuda_runtime.h>
#include <cstdint>

// Problem constants
#define BB   2
#define SS   2048
#define EE   2048
#define HQ   32
#define HKV  8
#define HD   64
#define KV   512
#define MM   (BB*SS)         // 4096
#define SCALE 0.125f         // 1/sqrt(64)
#define NSKT (SS/128)        // 16 sk tiles per row

// Scratch (device globals; no allocation allowed)
__device__ float g_Q[MM*EE];
__device__ float g_K[MM*KV];
__device__ float g_V[MM*KV];
__device__ float g_CTX[MM*EE];
__device__ float g_PART[BB*HQ*NSKT*SS];   // per-(bh, sk_tile, sq) partial row sums
__device__ float g_INV[BB*HQ*SS];         // 1/rowsum

// ---------------------------------------------------------------------------
// TF32 helpers
// ---------------------------------------------------------------------------
__device__ __forceinline__ uint32_t f2tf(float f) {
    uint32_t r;
    asm("cvt.rna.tf32.f32 %0, %1;" : "=r"(r) : "f"(f));
    return r;
}

__device__ __forceinline__ void mma8(float* c, const uint32_t* a, const uint32_t* b) {
    asm volatile(
        "mma.sync.aligned.m16n8k8.row.col.f32.tf32.tf32.f32 "
        "{%0,%1,%2,%3}, {%4,%5,%6,%7}, {%8,%9}, {%0,%1,%2,%3};\n"
        : "+f"(c[0]), "+f"(c[1]), "+f"(c[2]), "+f"(c[3])
        : "r"(a[0]), "r"(a[1]), "r"(a[2]), "r"(a[3]), "r"(b[0]), "r"(b[1]));
}

// ---------------------------------------------------------------------------
// Projection GEMM: C[M,N] = A[M,K] @ W[K,N] + bias
// BM=128, BN=128, BK=32; 8 warps (2x4); warp tile 64x32.
// ---------------------------------------------------------------------------
__global__ __launch_bounds__(256, 2) void proj_tf32_kernel(
    const float* __restrict__ A, const float* __restrict__ W,
    const float* __restrict__ bias, float* __restrict__ C,
    int M, int N, int K)
{
    __shared__ uint32_t As[128][36];    // [m][k]
    __shared__ uint32_t Ws[32][136];    // [k][n]

    const int tid  = threadIdx.x;
    const int row0 = blockIdx.y * 128;
    const int col0 = blockIdx.x * 128;
    const int warp = tid >> 5, lane = tid & 31;
    const int qr = lane >> 2, qc = lane & 3;
    const int wm = (warp >> 2) * 64, wn = (warp & 3) * 32;

    float acc[4][4][4] = {};

    for (int k0 = 0; k0 < K; k0 += 32) {
#pragma unroll
        for (int it = 0; it < 4; it++) {
            int idx = tid + it * 256;
            int r = idx >> 3, c = (idx & 7) * 4;
            float4 v = *(const float4*)&A[(size_t)(row0 + r) * K + k0 + c];
            *(uint4*)&As[r][c] = make_uint4(f2tf(v.x), f2tf(v.y), f2tf(v.z), f2tf(v.w));
        }
#pragma unroll
        for (int it = 0; it < 4; it++) {
            int idx = tid + it * 256;
            int r = idx >> 5, c = (idx & 31) * 4;
            float4 v = *(const float4*)&W[(size_t)(k0 + r) * N + col0 + c];
            *(uint4*)&Ws[r][c] = make_uint4(f2tf(v.x), f2tf(v.y), f2tf(v.z), f2tf(v.w));
        }
        __syncthreads();

#pragma unroll
        for (int kk = 0; kk < 32; kk += 8) {
            uint32_t a[4][4], b[4][2];
#pragma unroll
            for (int mi = 0; mi < 4; mi++) {
                int m = wm + mi * 16 + qr;
                a[mi][0] = As[m][kk + qc];
                a[mi][1] = As[m + 8][kk + qc];
                a[mi][2] = As[m][kk + qc + 4];
                a[mi][3] = As[m + 8][kk + qc + 4];
            }
#pragma unroll
            for (int ni = 0; ni < 4; ni++) {
                int n = wn + ni * 8 + qr;
                b[ni][0] = Ws[kk + qc][n];
                b[ni][1] = Ws[kk + qc + 4][n];
            }
#pragma unroll
            for (int mi = 0; mi < 4; mi++)
#pragma unroll
                for (int ni = 0; ni < 4; ni++)
                    mma8(acc[mi][ni], a[mi], b[ni]);
        }
        __syncthreads();
    }

#pragma unroll
    for (int mi = 0; mi < 4; mi++) {
        int row = row0 + wm + mi * 16 + qr;
#pragma unroll
        for (int ni = 0; ni < 4; ni++) {
            int col = col0 + wn + ni * 8 + 2 * qc;
            float2 bb = *(const float2*)&bias[col];
            float2 v0 = make_float2(acc[mi][ni][0] + bb.x, acc[mi][ni][1] + bb.y);
            float2 v1 = make_float2(acc[mi][ni][2] + bb.x, acc[mi][ni][3] + bb.y);
            *(float2*)&C[(size_t)row * N + col]       = v0;
            *(float2*)&C[(size_t)(row + 8) * N + col] = v1;
        }
    }
}

// ---------------------------------------------------------------------------
// Scores: attn[b,hq,sq,sk] = exp(scale * Q'[sq,:].K'[sk,:])  (UNNORMALIZED)
// Also emits deterministic per-block row partial sums to g_PART.
// ---------------------------------------------------------------------------
__global__ __launch_bounds__(256, 2) void scores_tf32_kernel(
    const float* __restrict__ Q, const float* __restrict__ Kp,
    float* __restrict__ attn, float* __restrict__ part)
{
    __shared__ uint32_t As[128][36];    // [sq][d]
    __shared__ uint32_t Bs[128][36];    // [sk][d]
    __shared__ float ssum[128][4];

    const int bh = blockIdx.z, b = bh >> 5, hq = bh & 31, hkv = hq >> 2;
    const int sq0 = blockIdx.y * 128, sk0 = blockIdx.x * 128;
    const int tid = threadIdx.x;
    const int warp = tid >> 5, lane = tid & 31;
    const int qr = lane >> 2, qc = lane & 3;
    const int wm = (warp >> 2) * 64, wn = (warp & 3) * 32;

    const float* Abase = Q  + (size_t)(b * SS + sq0) * EE + hq * HD;
    const float* Bbase = Kp + (size_t)(b * SS + sk0) * KV + hkv * HD;

    float acc[4][4][4] = {};

#pragma unroll
    for (int k0 = 0; k0 < 64; k0 += 32) {
#pragma unroll
        for (int it = 0; it < 4; it++) {
            int idx = tid + it * 256;
            int r = idx >> 3, c = (idx & 7) * 4;
            float4 v = *(const float4*)&Abase[(size_t)r * EE + k0 + c];
            *(uint4*)&As[r][c] = make_uint4(f2tf(v.x), f2tf(v.y), f2tf(v.z), f2tf(v.w));
        }
#pragma unroll
        for (int it = 0; it < 4; it++) {
            int idx = tid + it * 256;
            int r = idx >> 3, c = (idx & 7) * 4;
            float4 v = *(const float4*)&Bbase[(size_t)r * KV + k0 + c];
            *(uint4*)&Bs[r][c] = make_uint4(f2tf(v.x), f2tf(v.y), f2tf(v.z), f2tf(v.w));
        }
        __syncthreads();

#pragma unroll
        for (int kk = 0; kk < 32; kk += 8) {
            uint32_t a[4][4], bf[4][2];
#pragma unroll
            for (int mi = 0; mi < 4; mi++) {
                int m = wm + mi * 16 + qr;
                a[mi][0] = As[m][kk + qc];
                a[mi][1] = As[m + 8][kk + qc];
                a[mi][2] = As[m][kk + qc + 4];
                a[mi][3] = As[m + 8][kk + qc + 4];
            }
#pragma unroll
            for (int ni = 0; ni < 4; ni++) {
                int n = wn + ni * 8 + qr;
                bf[ni][0] = Bs[n][kk + qc];
                bf[ni][1] = Bs[n][kk + qc + 4];
            }
#pragma unroll
            for (int mi = 0; mi < 4; mi++)
#pragma unroll
                for (int ni = 0; ni < 4; ni++)
                    mma8(acc[mi][ni], a[mi], bf[ni]);
        }
        __syncthreads();
    }

    float* Cbase = attn + ((size_t)bh * SS + sq0) * SS + sk0;
#pragma unroll
    for (int mi = 0; mi < 4; mi++) {
        int row = wm + mi * 16 + qr;
        float s0 = 0.f, s1 = 0.f;
#pragma unroll
        for (int ni = 0; ni < 4; ni++) {
            int col = wn + ni * 8 + 2 * qc;
            float e0 = __expf(acc[mi][ni][0] * SCALE);
            float e1 = __expf(acc[mi][ni][1] * SCALE);
            float e2 = __expf(acc[mi][ni][2] * SCALE);
            float e3 = __expf(acc[mi][ni][3] * SCALE);
            *(float2*)&Cbase[(size_t)row * SS + col]       = make_float2(e0, e1);
            *(float2*)&Cbase[(size_t)(row + 8) * SS + col] = make_float2(e2, e3);
            s0 += e0 + e1;
            s1 += e2 + e3;
        }
        // reduce over the 4 lanes (qc) holding the same rows
        s0 += __shfl_xor_sync(0xffffffffu, s0, 1);
        s0 += __shfl_xor_sync(0xffffffffu, s0, 2);
        s1 += __shfl_xor_sync(0xffffffffu, s1, 1);
        s1 += __shfl_xor_sync(0xffffffffu, s1, 2);
        if (qc == 0) {
            ssum[row][warp & 3]     = s0;
            ssum[row + 8][warp & 3] = s1;
        }
    }
    __syncthreads();
    if (tid < 128) {
        float s = ssum[tid][0] + ssum[tid][1] + ssum[tid][2] + ssum[tid][3];
        part[((size_t)bh * NSKT + blockIdx.x) * SS + sq0 + tid] = s;
    }
}

// ---------------------------------------------------------------------------
// Finalize: inv[bh*SS + sq] = 1 / sum_t part[bh][t][sq]
// ---------------------------------------------------------------------------
__global__ __launch_bounds__(256) void finalize_kernel(
    const float* __restrict__ part, float* __restrict__ inv)
{
    int i = blockIdx.x * 256 + threadIdx.x;       // over BB*HQ*SS
    int bh = i >> 11, sq = i & (SS - 1);
    const float* p = part + (size_t)bh * NSKT * SS + sq;
    float s = 0.f;
#pragma unroll
    for (int t = 0; t < NSKT; t++) s += p[(size_t)t * SS];
    inv[i] = 1.0f / s;
}

// ---------------------------------------------------------------------------
// AV: normalize attn in place (attn *= inv[row]) while computing
// ctx[b,sq,hq*64+d] = sum_sk attn_norm[b,hq,sq,sk] * V[b,sk,hq/4,d]
// ---------------------------------------------------------------------------
__global__ __launch_bounds__(256, 2) void av_tf32_kernel(
    float* __restrict__ attn, const float* __restrict__ Vp,
    const float* __restrict__ inv, float* __restrict__ ctx)
{
    __shared__ uint32_t As[128][36];    // [sq][sk]
    __shared__ uint32_t Bs[64][33];     // [d][sk]

    const int bh = blockIdx.z, b = bh >> 5, hq = bh & 31, hkv = hq >> 2;
    const int sq0 = blockIdx.y * 128;
    const int tid = threadIdx.x;
    const int warp = tid >> 5, lane = tid & 31;
    const int qr = lane >> 2, qc = lane & 3;
    const int wm = (warp >> 1) * 32, wn = (warp & 1) * 32;

    float* Abase = attn + ((size_t)bh * SS + sq0) * SS;
    const float* Bbase = Vp + (size_t)(b * SS) * KV + hkv * HD;
    const float* ivb = inv + (size_t)bh * SS + sq0;

    float acc[2][4][4] = {};

    for (int k0 = 0; k0 < SS; k0 += 32) {
#pragma unroll
        for (int it = 0; it < 4; it++) {
            int idx = tid + it * 256;
            int r = idx >> 3, c = (idx & 7) * 4;
            float4 v = *(const float4*)&Abase[(size_t)r * SS + k0 + c];
            float iv = ivb[r];
            v.x *= iv; v.y *= iv; v.z *= iv; v.w *= iv;
            *(float4*)&Abase[(size_t)r * SS + k0 + c] = v;   // write normalized attn
            *(uint4*)&As[r][c] = make_uint4(f2tf(v.x), f2tf(v.y), f2tf(v.z), f2tf(v.w));
        }
        // V tile: 32(k) x 64(n), scalar coalesced loads, transposed store
#pragma unroll
        for (int it = 0; it < 8; it++) {
            int idx = tid + it * 256;
            int n = idx & 63, k = idx >> 6;
            Bs[n][k] = f2tf(Bbase[(size_t)(k0 + k) * KV + n]);
        }
        __syncthreads();

#pragma unroll
        for (int kk = 0; kk < 32; kk += 8) {
            uint32_t a[2][4], bf[4][2];
#pragma unroll
            for (int mi = 0; mi < 2; mi++) {
                int m = wm + mi * 16 + qr;
                a[mi][0] = As[m][kk + qc];
                a[mi][1] = As[m + 8][kk + qc];
                a[mi][2] = As[m][kk + qc + 4];
                a[mi][3] = As[m + 8][kk + qc + 4];
            }
#pragma unroll
            for (int ni = 0; ni < 4; ni++) {
                int n = wn + ni * 8 + qr;
                bf[ni][0] = Bs[n][kk + qc];
                bf[ni][1] = Bs[n][kk + qc + 4];
            }
#pragma unroll
            for (int mi = 0; mi < 2; mi++)
#pragma unroll
                for (int ni = 0; ni < 4; ni++)
                    mma8(acc[mi][ni], a[mi], bf[ni]);
        }
        __syncthreads();
    }

#pragma unroll
    for (int mi = 0; mi < 2; mi++) {
        int row = sq0 + wm + mi * 16 + qr;
#pragma unroll
        for (int ni = 0; ni < 4; ni++) {
            int col = wn + ni * 8 + 2 * qc;
            *(float2*)&ctx[(size_t)(b * SS + row) * EE + hq * HD + col] =
                make_float2(acc[mi][ni][0], acc[mi][ni][1]);
            *(float2*)&ctx[(size_t)(b * SS + row + 8) * EE + hq * HD + col] =
                make_float2(acc[mi][ni][2], acc[mi][ni][3]);
        }
    }
}

// ---------------------------------------------------------------------------
extern "C" void kernel_launch(void* const* d_in, const int* in_sizes, int n_in,
                              void* d_out, int out_size)
{
    const float* query = (const float*)d_in[0];
    const float* key   = (const float*)d_in[1];
    const float* value = (const float*)d_in[2];
    const float* Wq    = (const float*)d_in[3];
    const float* bq    = (const float*)d_in[4];
    const float* Wk    = (const float*)d_in[5];
    const float* bk    = (const float*)d_in[6];
    const float* Wv    = (const float*)d_in[7];
    const float* bv    = (const float*)d_in[8];
    const float* Wo    = (const float*)d_in[9];
    const float* bo    = (const float*)d_in[10];

    float* out  = (float*)d_out;                       // (B, S, E)
    float* attn = out + (size_t)BB * SS * EE;          // (B, HQ, S, S)

    float *qs, *ks, *vs, *cs, *ps, *is;
    cudaGetSymbolAddress((void**)&qs, g_Q);
    cudaGetSymbolAddress((void**)&ks, g_K);
    cudaGetSymbolAddress((void**)&vs, g_V);
    cudaGetSymbolAddress((void**)&cs, g_CTX);
    cudaGetSymbolAddress((void**)&ps, g_PART);
    cudaGetSymbolAddress((void**)&is, g_INV);

    // 1-3. Projections (TF32 tensor cores)
    proj_tf32_kernel<<<dim3(EE / 128, MM / 128), 256>>>(query, Wq, bq, qs, MM, EE, EE);
    proj_tf32_kernel<<<dim3(KV / 128, MM / 128), 256>>>(key,   Wk, bk, ks, MM, KV, EE);
    proj_tf32_kernel<<<dim3(KV / 128, MM / 128), 256>>>(value, Wv, bv, vs, MM, KV, EE);

    // 4. Scores -> unnormalized exp + partial row sums
    scores_tf32_kernel<<<dim3(NSKT, SS / 128, BB * HQ), 256>>>(qs, ks, attn, ps);

    // 5. Row-sum finalize
    finalize_kernel<<<dim3(BB * HQ * SS / 256), 256>>>(ps, is);

    // 6. attn @ V -> ctx ; normalizes attn in place
    av_tf32_kernel<<<dim3(1, SS / 128, BB * HQ), 256>>>(attn, vs, is, cs);

    // 7. Output projection -> out region of d_out
    proj_tf32_kernel<<<dim3(EE / 128, MM / 128), 256>>>(cs, Wo, bo, out, MM, EE, EE);
}